// round 3
// baseline (speedup 1.0000x reference)
#include <cuda_runtime.h>
#include <cstdint>
#include <math.h>

#define HH 128
#define WW 128
#define HW 16384
#define CC 16
#define NPTS 32
#define NLINES (5 * HW)
#define LOI_FLOATS (NLINES * (CC * NPTS))   // 81920 * 512 = 41,943,040
#define J_OFF LOI_FLOATS
#define S_OFF (LOI_FLOATS + 600)
#define TOPK 300
#define SORT_N 4096

// Scratch (allocation-free rules: __device__ globals)
__device__ float4 g_ft4[HW * 4];                 // features transposed to (H,W,C), C contiguous
__device__ unsigned long long g_keys[SORT_N];    // NMS candidate keys
__device__ int g_cnt;

// ---------------------------------------------------------------------------
// Kernel 1: transpose features (C,H,W) -> (H,W,C) as float4 groups; reset counter
// ---------------------------------------------------------------------------
__global__ void transpose_kernel(const float* __restrict__ f) {
    int p = blockIdx.x * blockDim.x + threadIdx.x;
    if (p == 0) g_cnt = 0;
    if (p < HW) {
#pragma unroll
        for (int j = 0; j < 4; j++) {
            float4 v;
            v.x = f[(4 * j + 0) * HW + p];
            v.y = f[(4 * j + 1) * HW + p];
            v.z = f[(4 * j + 2) * HW + p];
            v.w = f[(4 * j + 3) * HW + p];
            g_ft4[p * 4 + j] = v;
        }
    }
}

// ---------------------------------------------------------------------------
// Kernel 2: fused HAFM decode + LOI bilinear sampling. One warp per line.
// lane = t-index (0..31). Output layout out[l*512 + c*32 + t].
// ---------------------------------------------------------------------------
__global__ void __launch_bounds__(256) loi_kernel(
    const float* __restrict__ md,    // (3,H,W)
    const float* __restrict__ dis,   // (H,W)
    const float* __restrict__ res,   // (H,W)
    float* __restrict__ out)
{
    const int warp = threadIdx.x >> 5;
    const int lane = threadIdx.x & 31;
    const int l = blockIdx.x * (blockDim.x >> 5) + warp;
    if (l >= NLINES) return;

    const int r = l / HW;          // residual index 0..4, sign = r-2
    const int p = l - r * HW;      // pixel
    const int yi = p >> 7;
    const int xi = p & 127;

    // --- HAFM decoding (warp-uniform math; every lane computes the same) ---
    float dval = dis[p] + res[p] * (float)(r - 2);
    dval = fminf(fmaxf(dval, 0.0f), 1.0f);
    const float md0 = md[p];
    const float md1 = md[HW + p];
    const float md2 = md[2 * HW + p];

    const float md_un = (md0 - 0.5f) * 6.2831853071795864f;   // 2*pi
    float ss, cs;
    sincosf(md_un, &ss, &cs);
    const float yst = tanf(md1 * 1.5707963267948966f);
    const float yed = tanf(-md2 * 1.5707963267948966f);
    const float ds = dval * 5.0f;   // DIST_THRESHOLD

    const float fx = (float)xi, fy = (float)yi;
    const float ux = fminf(fmaxf((cs - ss * yst) * ds + fx, 0.0f), 127.0f);
    const float uy = fminf(fmaxf((ss + cs * yst) * ds + fy, 0.0f), 127.0f);
    const float vx = fminf(fmaxf((cs - ss * yed) * ds + fx, 0.0f), 127.0f);
    const float vy = fminf(fmaxf((ss + cs * yed) * ds + fy, 0.0f), 127.0f);

    // --- point for this lane ---
    const float t = (float)lane * (1.0f / 31.0f);
    const float px = ux * t + vx * (1.0f - t) - 0.5f;
    const float py = uy * t + vy * (1.0f - t) - 0.5f;

    const float px0 = fminf(fmaxf(floorf(px), 0.0f), 127.0f);
    const float py0 = fminf(fmaxf(floorf(py), 0.0f), 127.0f);
    const float px1 = fminf(px0 + 1.0f, 127.0f);
    const float py1 = fminf(py0 + 1.0f, 127.0f);

    const int ix0 = (int)px0, iy0 = (int)py0;
    const int ix1 = (int)px1, iy1 = (int)py1;

    const float w00 = (py1 - py) * (px1 - px);
    const float w10 = (py - py0) * (px1 - px);
    const float w01 = (py1 - py) * (px - px0);
    const float w11 = (py - py0) * (px - px0);

    const float4* __restrict__ f00 = g_ft4 + (iy0 * WW + ix0) * 4;
    const float4* __restrict__ f10 = g_ft4 + (iy1 * WW + ix0) * 4;
    const float4* __restrict__ f01 = g_ft4 + (iy0 * WW + ix1) * 4;
    const float4* __restrict__ f11 = g_ft4 + (iy1 * WW + ix1) * 4;

    float acc[CC];
#pragma unroll
    for (int j = 0; j < 4; j++) {
        float4 a = f00[j];
        float4 b = f10[j];
        float4 c = f01[j];
        float4 d = f11[j];
        acc[4 * j + 0] = w00 * a.x + w10 * b.x + w01 * c.x + w11 * d.x;
        acc[4 * j + 1] = w00 * a.y + w10 * b.y + w01 * c.y + w11 * d.y;
        acc[4 * j + 2] = w00 * a.z + w10 * b.z + w01 * c.z + w11 * d.z;
        acc[4 * j + 3] = w00 * a.w + w10 * b.w + w01 * c.w + w11 * d.w;
    }

    float* __restrict__ o = out + (size_t)l * (CC * NPTS) + lane;
#pragma unroll
    for (int c = 0; c < CC; c++)
        o[c * NPTS] = acc[c];   // 32 lanes -> 128B coalesced store per c
}

// ---------------------------------------------------------------------------
// Kernel 3: 3x3 NMS; compact positive local maxima into key list.
// key = (float_bits << 32) | (0xFFFFFFFF - idx)  -> desc order = value desc, idx asc
// ---------------------------------------------------------------------------
__global__ void nms_kernel(const float* __restrict__ jloc) {
    int p = blockIdx.x * blockDim.x + threadIdx.x;
    if (p >= HW) return;
    int y = p >> 7, x = p & 127;
    float a = jloc[p];
    float m = -INFINITY;
#pragma unroll
    for (int dy = -1; dy <= 1; dy++) {
#pragma unroll
        for (int dx = -1; dx <= 1; dx++) {
            int yy = y + dy, xx = x + dx;
            if (yy >= 0 && yy < HH && xx >= 0 && xx < WW)
                m = fmaxf(m, jloc[yy * WW + xx]);
        }
    }
    if (a == m && a > 0.0f) {
        int pos = atomicAdd(&g_cnt, 1);
        if (pos < SORT_N) {
            unsigned long long key =
                ((unsigned long long)__float_as_uint(a) << 32) |
                (unsigned long long)(0xFFFFFFFFu - (unsigned)p);
            g_keys[pos] = key;
        }
    }
}

// ---------------------------------------------------------------------------
// Kernel 4: rank-by-counting top-K. No sort. Each thread owns one candidate,
// counts strictly-greater keys (all keys distinct: idx embedded), writes its
// junction/score directly to output slot = rank if rank < TOPK.
// 16 blocks x 256 threads; every block stages all keys in shared.
// ---------------------------------------------------------------------------
__global__ void __launch_bounds__(256) rank_topk_kernel(
    const float* __restrict__ joff, float* __restrict__ out)
{
    __shared__ unsigned long long s[SORT_N];
    const int tid = threadIdx.x;
    const int gid = blockIdx.x * 256 + tid;

    int cnt = g_cnt;
    if (cnt > SORT_N) cnt = SORT_N;
    // pad to multiple of 8 with 0 (0 is never > any real key: value bits > 0)
    const int cnt_pad = (cnt + 7) & ~7;

    for (int i = tid; i < cnt_pad; i += 256)
        s[i] = (i < cnt) ? g_keys[i] : 0ULL;
    __syncthreads();

    if (gid >= cnt) return;
    const unsigned long long mykey = s[gid];

    int rank = 0;
#pragma unroll 4
    for (int j = 0; j < cnt_pad; j += 2) {
        // LDS.128 pair
        unsigned long long a = s[j], b = s[j + 1];
        rank += (a > mykey) + (b > mykey);
    }

    if (rank < TOPK) {
        unsigned idx = 0xFFFFFFFFu - (unsigned)(mykey & 0xFFFFFFFFull);
        float val = __uint_as_float((unsigned)(mykey >> 32));
        float fy = (float)(idx >> 7);
        float fx = (float)(idx & 127);
        out[J_OFF + 2 * rank + 0] = fx + joff[idx] + 0.5f;        // x
        out[J_OFF + 2 * rank + 1] = fy + joff[HW + idx] + 0.5f;   // y
        out[S_OFF + rank] = val;
    }
}

// ---------------------------------------------------------------------------
extern "C" void kernel_launch(void* const* d_in, const int* in_sizes, int n_in,
                              void* d_out, int out_size) {
    const float* md   = (const float*)d_in[0];   // (1,3,128,128)
    const float* dis  = (const float*)d_in[1];   // (1,1,128,128)
    const float* res  = (const float*)d_in[2];   // (1,1,128,128)
    const float* feat = (const float*)d_in[3];   // (16,128,128)
    const float* jloc = (const float*)d_in[4];   // (1,128,128)
    const float* joff = (const float*)d_in[5];   // (2,128,128)
    float* out = (float*)d_out;

    transpose_kernel<<<(HW + 255) / 256, 256>>>(feat);
    loi_kernel<<<NLINES / 8, 256>>>(md, dis, res, out);
    nms_kernel<<<(HW + 255) / 256, 256>>>(jloc);
    rank_topk_kernel<<<SORT_N / 256, 256>>>(joff, out);
}

// round 4
// speedup vs baseline: 1.3306x; 1.3306x over previous
#include <cuda_runtime.h>
#include <cstdint>
#include <math.h>

#define HH 128
#define WW 128
#define HW 16384
#define CC 16
#define NPTS 32
#define NLINES (5 * HW)
#define LOI_FLOATS (NLINES * (CC * NPTS))   // 81920 * 512 = 41,943,040
#define J_OFF LOI_FLOATS
#define S_OFF (LOI_FLOATS + 600)
#define TOPK 300
#define NSEG 64                              // prep grid blocks (16384/256)
#define MAXCAND 4096

// ---- device scratch (allocation-free rules) ----
__device__ float4 g_ft4[HW * 4];             // features transposed (H,W,C)
__device__ float4 g_geom[NLINES];            // per-line (ux,uy,vx,vy)
__device__ unsigned long long g_keys[NSEG * 256];  // per-block candidate segments
__device__ int g_bcnt[NSEG];                 // per-block candidate counts

// ---- packed f32x2 helpers (sm_100+) ----
__device__ __forceinline__ unsigned long long pk2(float lo, float hi) {
    unsigned long long r;
    asm("mov.b64 %0, {%1, %2};" : "=l"(r) : "f"(lo), "f"(hi));
    return r;
}
__device__ __forceinline__ unsigned long long mul2(unsigned long long a, unsigned long long b) {
    unsigned long long d;
    asm("mul.rn.f32x2 %0, %1, %2;" : "=l"(d) : "l"(a), "l"(b));
    return d;
}
__device__ __forceinline__ unsigned long long fma2(unsigned long long a, unsigned long long b,
                                                   unsigned long long c) {
    unsigned long long d;
    asm("fma.rn.f32x2 %0, %1, %2, %3;" : "=l"(d) : "l"(a), "l"(b), "l"(c));
    return d;
}
__device__ __forceinline__ float2 up2(unsigned long long v) {
    float2 r;
    asm("mov.b64 {%0, %1}, %2;" : "=f"(r.x), "=f"(r.y) : "l"(v));
    return r;
}

// ---------------------------------------------------------------------------
// Kernel 1 (prep): feature transpose + line geometry (trig once per PIXEL,
// not per lane!) + 3x3 NMS with per-block candidate compaction.
// Grid: 64 blocks x 256 threads, one thread per pixel.
// ---------------------------------------------------------------------------
__global__ void __launch_bounds__(256) prep_kernel(
    const float* __restrict__ f,     // (16,H,W)
    const float* __restrict__ md,    // (3,H,W)
    const float* __restrict__ dis,   // (H,W)
    const float* __restrict__ res,   // (H,W)
    const float* __restrict__ jloc)  // (H,W)
{
    __shared__ int s_cnt;
    const int tid = threadIdx.x;
    const int p = blockIdx.x * 256 + tid;
    if (tid == 0) s_cnt = 0;
    __syncthreads();

    const int yi = p >> 7;
    const int xi = p & 127;

    // --- transpose features: (C,H,W) -> (H,W,C) ---
#pragma unroll
    for (int j = 0; j < 4; j++) {
        float4 v;
        v.x = f[(4 * j + 0) * HW + p];
        v.y = f[(4 * j + 1) * HW + p];
        v.z = f[(4 * j + 2) * HW + p];
        v.w = f[(4 * j + 3) * HW + p];
        g_ft4[p * 4 + j] = v;
    }

    // --- line geometry: trig shared across the 5 residuals ---
    const float md0 = md[p];
    const float md1 = md[HW + p];
    const float md2 = md[2 * HW + p];
    const float d0  = dis[p];
    const float rs  = res[p];

    float ss, cs;
    sincosf((md0 - 0.5f) * 6.2831853071795864f, &ss, &cs);
    const float yst = tanf(md1 * 1.5707963267948966f);
    const float yed = tanf(-md2 * 1.5707963267948966f);
    const float ax = cs - ss * yst, ay = ss + cs * yst;   // start direction
    const float bx = cs - ss * yed, by = ss + cs * yed;   // end direction
    const float fx = (float)xi, fy = (float)yi;

#pragma unroll
    for (int r = 0; r < 5; r++) {
        float dval = fminf(fmaxf(d0 + rs * (float)(r - 2), 0.0f), 1.0f);
        const float ds = dval * 5.0f;
        float4 g;
        g.x = fminf(fmaxf(ax * ds + fx, 0.0f), 127.0f);   // ux
        g.y = fminf(fmaxf(ay * ds + fy, 0.0f), 127.0f);   // uy
        g.z = fminf(fmaxf(bx * ds + fx, 0.0f), 127.0f);   // vx
        g.w = fminf(fmaxf(by * ds + fy, 0.0f), 127.0f);   // vy
        g_geom[r * HW + p] = g;
    }

    // --- 3x3 NMS, compact into this block's segment ---
    float a = jloc[p];
    float m = -INFINITY;
#pragma unroll
    for (int dy = -1; dy <= 1; dy++) {
#pragma unroll
        for (int dx = -1; dx <= 1; dx++) {
            int yy = yi + dy, xx = xi + dx;
            if (yy >= 0 && yy < HH && xx >= 0 && xx < WW)
                m = fmaxf(m, jloc[yy * WW + xx]);
        }
    }
    if (a == m && a > 0.0f) {
        int pos = atomicAdd(&s_cnt, 1);
        g_keys[blockIdx.x * 256 + pos] =
            ((unsigned long long)__float_as_uint(a) << 32) |
            (unsigned long long)(0xFFFFFFFFu - (unsigned)p);
    }
    __syncthreads();
    if (tid == 0) g_bcnt[blockIdx.x] = s_cnt;
}

// ---------------------------------------------------------------------------
// Kernel 2 (loi): one warp per line, lane = t. Geometry precomputed.
// ---------------------------------------------------------------------------
__global__ void __launch_bounds__(256) loi_kernel(float* __restrict__ out)
{
    const int warp = threadIdx.x >> 5;
    const int lane = threadIdx.x & 31;
    const int l = blockIdx.x * 8 + warp;

    const float4 g = g_geom[l];      // broadcast LDG.128

    const float t = (float)lane * (1.0f / 31.0f);
    const float omt = 1.0f - t;
    const float px = g.x * t + g.z * omt - 0.5f;
    const float py = g.y * t + g.w * omt - 0.5f;

    const float px0 = fminf(fmaxf(floorf(px), 0.0f), 127.0f);
    const float py0 = fminf(fmaxf(floorf(py), 0.0f), 127.0f);
    const float px1 = fminf(px0 + 1.0f, 127.0f);
    const float py1 = fminf(py0 + 1.0f, 127.0f);

    const int ix0 = (int)px0, iy0 = (int)py0;
    const int ix1 = (int)px1, iy1 = (int)py1;

    const unsigned long long w00 = pk2((py1 - py) * (px1 - px), (py1 - py) * (px1 - px));
    const unsigned long long w10 = pk2((py - py0) * (px1 - px), (py - py0) * (px1 - px));
    const unsigned long long w01 = pk2((py1 - py) * (px - px0), (py1 - py) * (px - px0));
    const unsigned long long w11 = pk2((py - py0) * (px - px0), (py - py0) * (px - px0));

    const ulonglong2* __restrict__ f00 = (const ulonglong2*)(g_ft4 + (iy0 * WW + ix0) * 4);
    const ulonglong2* __restrict__ f10 = (const ulonglong2*)(g_ft4 + (iy1 * WW + ix0) * 4);
    const ulonglong2* __restrict__ f01 = (const ulonglong2*)(g_ft4 + (iy0 * WW + ix1) * 4);
    const ulonglong2* __restrict__ f11 = (const ulonglong2*)(g_ft4 + (iy1 * WW + ix1) * 4);

    unsigned long long acc[8];
#pragma unroll
    for (int j = 0; j < 4; j++) {
        ulonglong2 a = f00[j];
        ulonglong2 b = f10[j];
        ulonglong2 c = f01[j];
        ulonglong2 d = f11[j];
        unsigned long long t0 = mul2(a.x, w00);
        t0 = fma2(b.x, w10, t0);
        t0 = fma2(c.x, w01, t0);
        acc[2 * j + 0] = fma2(d.x, w11, t0);
        unsigned long long t1 = mul2(a.y, w00);
        t1 = fma2(b.y, w10, t1);
        t1 = fma2(c.y, w01, t1);
        acc[2 * j + 1] = fma2(d.y, w11, t1);
    }

    float* __restrict__ o = out + (size_t)l * (CC * NPTS) + lane;
#pragma unroll
    for (int k = 0; k < 8; k++) {
        float2 v = up2(acc[k]);
        __stcs(o + (2 * k + 0) * NPTS, v.x);   // streaming: don't pollute L2
        __stcs(o + (2 * k + 1) * NPTS, v.y);
    }
}

// ---------------------------------------------------------------------------
// Kernel 3 (topk): compact segments into shared, rank-by-counting, direct emit.
// 16 blocks x 256 threads.
// ---------------------------------------------------------------------------
__global__ void __launch_bounds__(256) topk_kernel(
    const float* __restrict__ joff, float* __restrict__ out)
{
    __shared__ alignas(16) unsigned long long s[MAXCAND + 4];
    __shared__ int s_bc[NSEG];
    __shared__ int s_ps[NSEG + 1];
    const int tid = threadIdx.x;

    if (tid < NSEG) s_bc[tid] = g_bcnt[tid];
    __syncthreads();
    if (tid == 0) {
        int acc = 0;
#pragma unroll
        for (int b = 0; b < NSEG; b++) { s_ps[b] = acc; acc += s_bc[b]; }
        s_ps[NSEG] = acc;
    }
    __syncthreads();

    int cnt = s_ps[NSEG];
    if (cnt > MAXCAND) cnt = MAXCAND;
    const int cnt_pad = (cnt + 3) & ~3;

    // compact copy (segments are <=256 long; one pass per segment)
#pragma unroll 1
    for (int b = 0; b < NSEG; b++) {
        int bc = s_bc[b];
        int dst = s_ps[b] + tid;
        if (tid < bc && dst < MAXCAND)
            s[dst] = g_keys[b * 256 + tid];
    }
    if (tid < 4) s[cnt + tid] = 0ULL;   // pad (0 < any real key)
    __syncthreads();

    const int gid = blockIdx.x * 256 + tid;
    if (gid >= cnt) return;
    const unsigned long long mykey = s[gid];

    const ulonglong2* sp = (const ulonglong2*)s;
    int rank = 0;
#pragma unroll 4
    for (int i = 0; i < cnt_pad / 2; i++) {
        ulonglong2 v = sp[i];                   // LDS.128 broadcast
        rank += (v.x > mykey) + (v.y > mykey);
    }

    if (rank < TOPK) {
        unsigned idx = 0xFFFFFFFFu - (unsigned)(mykey & 0xFFFFFFFFull);
        float val = __uint_as_float((unsigned)(mykey >> 32));
        float fy = (float)(idx >> 7);
        float fx = (float)(idx & 127);
        out[J_OFF + 2 * rank + 0] = fx + joff[idx] + 0.5f;
        out[J_OFF + 2 * rank + 1] = fy + joff[HW + idx] + 0.5f;
        out[S_OFF + rank] = val;
    }
}

// ---------------------------------------------------------------------------
extern "C" void kernel_launch(void* const* d_in, const int* in_sizes, int n_in,
                              void* d_out, int out_size) {
    const float* md   = (const float*)d_in[0];   // (1,3,128,128)
    const float* dis  = (const float*)d_in[1];   // (1,1,128,128)
    const float* res  = (const float*)d_in[2];   // (1,1,128,128)
    const float* feat = (const float*)d_in[3];   // (16,128,128)
    const float* jloc = (const float*)d_in[4];   // (1,128,128)
    const float* joff = (const float*)d_in[5];   // (2,128,128)
    float* out = (float*)d_out;

    prep_kernel<<<NSEG, 256>>>(feat, md, dis, res, jloc);
    loi_kernel<<<NLINES / 8, 256>>>(out);
    topk_kernel<<<16, 256>>>(joff, out);
}